// round 13
// baseline (speedup 1.0000x reference)
#include <cuda_runtime.h>
#include <cuda_fp16.h>
#include <math.h>
#include <stdint.h>

// Problem constants
#define Bv   2
#define Tv   2048
#define Dm   1024
#define NH   16
#define NKV  4
#define HD   64
#define WIN  128
#define Mtok (Bv*Tv)        // 4096
#define DFF  (4*Dm)         // 4096
#define NQKV 1536           // 1024 Q + 256 K + 256 V

// ---------------- scratch (device globals) ---------------------------------
__device__ __align__(256) __half g_Xhi[Mtok*Dm],  g_Xlo[Mtok*Dm];
__device__ __align__(256) __half g_Wqkv[NQKV*Dm];
__device__ __align__(256) __half g_W1[(size_t)DFF*Dm];
__device__ __align__(256) __half g_W2[(size_t)Dm*DFF];
__device__ __align__(256) __half g_AOhi[Mtok*Dm], g_AOlo[Mtok*Dm];
__device__ __align__(256) __half g_H1hi[(size_t)Mtok*DFF], g_H1lo[(size_t)Mtok*DFF];
__device__ __align__(256) float g_QKVlin[(size_t)Mtok*NQKV];
__device__ __align__(256) float g_AO[Mtok*Dm];
__device__ float g_cosT[Tv*32], g_sinT[Tv*32];

// ---------------- helpers ---------------------------------------------------
__device__ __forceinline__ uint32_t smem_u32(const void* p) {
    uint32_t a;
    asm("{ .reg .u64 t; cvta.to.shared.u64 t, %1; cvt.u32.u64 %0, t; }" : "=r"(a) : "l"(p));
    return a;
}
#define LDMX4(r0,r1,r2,r3,addr) \
    asm volatile("ldmatrix.sync.aligned.m8n8.x4.shared.b16 {%0,%1,%2,%3}, [%4];" \
        : "=r"(r0), "=r"(r1), "=r"(r2), "=r"(r3) : "r"(addr))
#define MMA16816(d, a, b) \
    asm volatile("mma.sync.aligned.m16n8k16.row.col.f32.f16.f16.f32 " \
        "{%0,%1,%2,%3}, {%4,%5,%6,%7}, {%8,%9}, {%0,%1,%2,%3};" \
        : "+f"((d)[0]), "+f"((d)[1]), "+f"((d)[2]), "+f"((d)[3]) \
        : "r"((a)[0]), "r"((a)[1]), "r"((a)[2]), "r"((a)[3]), "r"((b)[0]), "r"((b)[1]))

__device__ __forceinline__ uint32_t pack_h2(float x, float y) {
    __half2 h = __floats2half2_rn(x, y);
    return *(uint32_t*)&h;
}

// ---------------- warp-MMA fp16 asymmetric-split GEMM -----------------------
// C[M,N] = A[M,K] @ B[N,K]^T with A = Ahi+Alo (fp16 pair), B = Bh (fp16).
// Two MMA passes: Ahi@Bh + Alo@Bh = A@Bh exactly (fp32 accumulate).
// EPI 0: write fp32 Cf.  EPI 1: write SiLU(acc) split to fp16 Chi/Clo.
#define GBM 128
#define GBN 128
#define GBK 32
#define KP  40                      // padded row length (halves) -> 80B stride
#define TILEB (128*KP*2)            // 10240 B per tile
#define STAGE (3*TILEB)             // Ahi, Alo, Bh
#define GEMM_SMEM (3*STAGE)         // 92160 B (3-stage pipeline)

template<int EPI>
__global__ __launch_bounds__(256,2)
void mma_gemm(const __half* __restrict__ Ahi, const __half* __restrict__ Alo,
              const __half* __restrict__ Bh,
              float* __restrict__ Cf,
              __half* __restrict__ Chi, __half* __restrict__ Clo,
              int M, int N, int K)
{
    extern __shared__ char dsm[];
    const uint32_t sbase = smem_u32(dsm);
    const int tid   = threadIdx.x;
    const int lane  = tid & 31;
    const int wid   = tid >> 5;
    const int warpM = wid & 1;          // 2 x 64 rows
    const int warpN = wid >> 1;         // 4 x 32 cols
    const int bm    = blockIdx.y * GBM;
    const int bn    = blockIdx.x * GBN;

    const __half* gp[3] = {Ahi, Alo, Bh};

    // 1536 16B chunks per stage (3 tiles x 128 rows x 4 segs)
    auto load_stage = [&](int chunk, int buf) {
        const uint32_t st = sbase + buf * STAGE;
        const int k0 = chunk * GBK;
        #pragma unroll
        for (int i = 0; i < 6; i++) {
            int c   = i * 256 + tid;
            int t3  = c >> 9;
            int r   = (c >> 2) & 127;
            int s   = c & 3;
            int grow = (t3 < 2 ? bm : bn) + r;
            const char* src = (const char*)(gp[t3] + (size_t)grow * K + k0 + s * 8);
            uint32_t dst = st + t3 * TILEB + r * (KP * 2) + s * 16;
            asm volatile("cp.async.cg.shared.global [%0], [%1], 16;" :: "r"(dst), "l"(src));
        }
        asm volatile("cp.async.commit_group;" ::: "memory");
    };

    float acc[4][4][4];
    #pragma unroll
    for (int i = 0; i < 4; i++)
        #pragma unroll
        for (int j = 0; j < 4; j++)
            #pragma unroll
            for (int q = 0; q < 4; q++) acc[i][j][q] = 0.f;

    const int arow = (lane & 7) + 8 * ((lane >> 3) & 1);
    const int acol = 8 * (lane >> 4);
    const int brow = (lane & 7) + 8 * (lane >> 4);
    const int bcol = 8 * ((lane >> 3) & 1);

    const int C = K / GBK;
    load_stage(0, 0);
    load_stage(1, 1);

    for (int c = 0; c < C; c++) {
        const int buf = c % 3;
        if (c + 2 < C) load_stage(c + 2, (c + 2) % 3);

        if (c + 2 < C)      asm volatile("cp.async.wait_group 2;" ::: "memory");
        else if (c + 1 < C) asm volatile("cp.async.wait_group 1;" ::: "memory");
        else                asm volatile("cp.async.wait_group 0;" ::: "memory");
        __syncthreads();

        const uint32_t sAh = sbase + buf * STAGE;
        const uint32_t sAl = sAh + TILEB;
        const uint32_t sBh = sAh + 2 * TILEB;

        #pragma unroll
        for (int ks = 0; ks < 2; ks++) {
            const int kb = ks * 16;
            uint32_t a[4][4], bh[4][2];

            #pragma unroll
            for (int nf2 = 0; nf2 < 2; nf2++) {
                uint32_t bd = sBh + (((warpN * 32 + nf2 * 16 + brow) * KP) + kb + bcol) * 2;
                LDMX4(bh[nf2*2][0], bh[nf2*2][1], bh[nf2*2+1][0], bh[nf2*2+1][1], bd);
            }
            #pragma unroll
            for (int mf = 0; mf < 4; mf++) {
                uint32_t ad = sAh + (((warpM * 64 + mf * 16 + arow) * KP) + kb + acol) * 2;
                LDMX4(a[mf][0], a[mf][1], a[mf][2], a[mf][3], ad);
            }
            #pragma unroll
            for (int mf = 0; mf < 4; mf++)
                #pragma unroll
                for (int nf = 0; nf < 4; nf++)
                    MMA16816(acc[mf][nf], a[mf], bh[nf]);       // hi_a x B

            #pragma unroll
            for (int mf = 0; mf < 4; mf++) {
                uint32_t ad = sAl + (((warpM * 64 + mf * 16 + arow) * KP) + kb + acol) * 2;
                LDMX4(a[mf][0], a[mf][1], a[mf][2], a[mf][3], ad);
            }
            #pragma unroll
            for (int mf = 0; mf < 4; mf++)
                #pragma unroll
                for (int nf = 0; nf < 4; nf++)
                    MMA16816(acc[mf][nf], a[mf], bh[nf]);       // lo_a x B
        }
        __syncthreads();
    }

    const int g = lane >> 2, i4 = lane & 3;
    #pragma unroll
    for (int mf = 0; mf < 4; mf++) {
        #pragma unroll
        for (int nf = 0; nf < 4; nf++) {
            int row0 = bm + warpM * 64 + mf * 16 + g;
            int col  = bn + warpN * 32 + nf * 8 + 2 * i4;
            float d0 = acc[mf][nf][0], d1 = acc[mf][nf][1];
            float d2 = acc[mf][nf][2], d3 = acc[mf][nf][3];
            if (EPI == 0) {
                *(float2*)&Cf[(size_t)row0 * N + col]       = make_float2(d0, d1);
                *(float2*)&Cf[(size_t)(row0 + 8) * N + col] = make_float2(d2, d3);
            } else {
                float a0 = d0 / (1.f + __expf(-d0));
                float a1 = d1 / (1.f + __expf(-d1));
                float a2 = d2 / (1.f + __expf(-d2));
                float a3 = d3 / (1.f + __expf(-d3));
                __half h0 = __float2half_rn(a0), h1 = __float2half_rn(a1);
                __half h2 = __float2half_rn(a2), h3 = __float2half_rn(a3);
                __half l0 = __float2half_rn(a0 - __half2float(h0));
                __half l1 = __float2half_rn(a1 - __half2float(h1));
                __half l2 = __float2half_rn(a2 - __half2float(h2));
                __half l3 = __float2half_rn(a3 - __half2float(h3));
                *(__half2*)&Chi[(size_t)row0 * N + col]       = __halves2half2(h0, h1);
                *(__half2*)&Chi[(size_t)(row0 + 8) * N + col] = __halves2half2(h2, h3);
                *(__half2*)&Clo[(size_t)row0 * N + col]       = __halves2half2(l0, l1);
                *(__half2*)&Clo[(size_t)(row0 + 8) * N + col] = __halves2half2(l2, l3);
            }
        }
    }
}

// ---------------- fp32 -> fp16 hi/lo split (8 floats/thread) ---------------
__global__ void split_kernel(const float4* __restrict__ in,
                             uint4* __restrict__ hi,
                             uint4* __restrict__ lo, int n)
{
    int i = blockIdx.x * 256 + threadIdx.x;       // handles 8 floats
    if (i * 8 >= n) return;
    float4 v0 = in[2*i], v1 = in[2*i+1];
    float f[8] = {v0.x, v0.y, v0.z, v0.w, v1.x, v1.y, v1.z, v1.w};
    float hf[8], lf[8];
    #pragma unroll
    for (int k = 0; k < 8; k++) {
        hf[k] = __half2float(__float2half_rn(f[k]));
        lf[k] = f[k] - hf[k];
    }
    uint4 H, L;
    H.x = pack_h2(hf[0], hf[1]); H.y = pack_h2(hf[2], hf[3]);
    H.z = pack_h2(hf[4], hf[5]); H.w = pack_h2(hf[6], hf[7]);
    L.x = pack_h2(lf[0], lf[1]); L.y = pack_h2(lf[2], lf[3]);
    L.z = pack_h2(lf[4], lf[5]); L.w = pack_h2(lf[6], lf[7]);
    hi[i] = H;
    lo[i] = L;
}

// ---------------- fp32 -> fp16 convert (8 floats/thread) -------------------
__global__ void cvt_kernel(const float4* __restrict__ in, uint4* __restrict__ out, int n)
{
    int i = blockIdx.x * 256 + threadIdx.x;
    if (i * 8 >= n) return;
    float4 v0 = in[2*i], v1 = in[2*i+1];
    uint4 O;
    O.x = pack_h2(v0.x, v0.y); O.y = pack_h2(v0.z, v0.w);
    O.z = pack_h2(v1.x, v1.y); O.w = pack_h2(v1.z, v1.w);
    out[i] = O;
}

// ---------------- RoPE table ------------------------------------------------
__global__ void rope_table_kernel()
{
    int idx = blockIdx.x * 256 + threadIdx.x;
    if (idx >= Tv * 32) return;
    int t = idx >> 5, d = idx & 31;
    double invf = pow(10000.0, -(double)d / 32.0);
    double ang  = fmod((double)t * invf, 6.283185307179586476925287);
    g_cosT[idx] = (float)cos(ang);
    g_sinT[idx] = (float)sin(ang);
}

// ---------------- sliding-window GQA attention v3 --------------------------
// Reads QKVlin directly (token-major), applies RoPE to Q/K on the fly.
// One block = 4 q-heads (one kv head) x 8 queries, 512 threads (16 warps);
// each warp serially processes 2 queries of its head.
#define QB   8
#define NR   (WIN + QB - 1)    // 135
#define KSTR 68
#define ATTN_SMEM ((NR*KSTR + NR*HD + 4*QB*HD) * (int)sizeof(float))  // 79472

__global__ __launch_bounds__(512) void attn_kernel(const float* __restrict__ QKV,
                                                   float* __restrict__ O)
{
    extern __shared__ float smem[];
    float* Ks = smem;                    // [NR][KSTR]  (roped K)
    float* Vs = Ks + NR * KSTR;          // [NR][64]
    float* Qs = Vs + NR * HD;            // [4][QB][64] (roped Q)

    const int b    = blockIdx.z;
    const int kvh  = blockIdx.y;
    const int qs   = blockIdx.x * QB;
    const int tid  = threadIdx.x;
    const int lane = tid & 31;
    const int wid  = tid >> 5;           // 16 warps
    const int hh   = wid >> 2;           // head within kv group (0..3)
    const int wq   = wid & 3;            // base query index

    const int kbase = qs - (WIN - 1);

    // K rows: rope pairs (d, d+32)
    for (int idx = tid; idx < NR * 32; idx += 512) {
        int j = idx >> 5, d = idx & 31;
        int kidx = kbase + j;
        float o1 = 0.f, o2 = 0.f;
        if (kidx >= 0) {
            const float* row = QKV + (size_t)(b * Tv + kidx) * NQKV + 1024 + kvh * HD;
            float x1 = row[d], x2 = row[d + 32];
            float cs = g_cosT[kidx * 32 + d], sn = g_sinT[kidx * 32 + d];
            o1 = x1 * cs - x2 * sn;
            o2 = x1 * sn + x2 * cs;
        }
        Ks[j * KSTR + d]      = o1;
        Ks[j * KSTR + d + 32] = o2;
    }
    // V rows: plain gather
    for (int idx = tid; idx < NR * HD; idx += 512) {
        int j = idx >> 6, d = idx & 63;
        int kidx = kbase + j;
        float vv = 0.f;
        if (kidx >= 0)
            vv = QKV[(size_t)(b * Tv + kidx) * NQKV + 1280 + kvh * HD + d];
        Vs[j * HD + d] = vv;
    }
    // Q rows (4 heads x QB): rope
    for (int idx = tid; idx < 4 * QB * 32; idx += 512) {
        int hl = idx >> 8, r = (idx >> 5) & 7, d = idx & 31;
        int t = qs + r;
        const float* row = QKV + (size_t)(b * Tv + t) * NQKV + (kvh * 4 + hl) * HD;
        float x1 = row[d], x2 = row[d + 32];
        float cs = g_cosT[t * 32 + d], sn = g_sinT[t * 32 + d];
        Qs[(hl * QB + r) * HD + d]      = x1 * cs - x2 * sn;
        Qs[(hl * QB + r) * HD + d + 32] = x1 * sn + x2 * cs;
    }
    __syncthreads();

    const int h = kvh * 4 + hh;
    #pragma unroll
    for (int qq = 0; qq < 2; qq++) {
        const int wr = wq + qq * 4;
        const int qi = qs + wr;

        float4 qreg[16];
        const float4* q4 = (const float4*)(Qs + (hh * QB + wr) * HD);
        #pragma unroll
        for (int i = 0; i < 16; i++) qreg[i] = q4[i];

        float sc[4];
        #pragma unroll
        for (int c = 0; c < 4; c++) {
            int l = lane + 32 * c;
            int kidx = qi - (WIN - 1) + l;
            if (kidx >= 0) {
                const float4* k4 = (const float4*)(Ks + (wr + l) * KSTR);
                float acc = 0.f;
                #pragma unroll
                for (int i = 0; i < 16; i++) {
                    float4 kk = k4[i];
                    acc += qreg[i].x*kk.x + qreg[i].y*kk.y + qreg[i].z*kk.z + qreg[i].w*kk.w;
                }
                sc[c] = acc * 0.125f;
            } else {
                sc[c] = -INFINITY;
            }
        }

        float m = fmaxf(fmaxf(sc[0], sc[1]), fmaxf(sc[2], sc[3]));
        #pragma unroll
        for (int off = 16; off >= 1; off >>= 1)
            m = fmaxf(m, __shfl_xor_sync(0xffffffffu, m, off));
        float p[4]; float sum = 0.f;
        #pragma unroll
        for (int c = 0; c < 4; c++) { p[c] = __expf(sc[c] - m); sum += p[c]; }
        #pragma unroll
        for (int off = 16; off >= 1; off >>= 1)
            sum += __shfl_xor_sync(0xffffffffu, sum, off);
        const float inv = 1.f / sum;
        #pragma unroll
        for (int c = 0; c < 4; c++) p[c] *= inv;

        float o0 = 0.f, o1 = 0.f;
        #pragma unroll 4
        for (int l = 0; l < WIN; l++) {
            float w = __shfl_sync(0xffffffffu, p[l >> 5], l & 31);
            const float* vrow = Vs + (wr + l) * HD;
            o0 = fmaf(w, vrow[lane],      o0);
            o1 = fmaf(w, vrow[lane + 32], o1);
        }
        float* orow = O + ((size_t)(b * Tv + qi)) * Dm + h * HD;
        orow[lane]      = o0;
        orow[lane + 32] = o1;
    }
}

// ---------------- launch ----------------------------------------------------
extern "C" void kernel_launch(void* const* d_in, const int* in_sizes, int n_in,
                              void* d_out, int out_size)
{
    const float* X  = (const float*)d_in[0];
    const float* Wq = (const float*)d_in[1];
    const float* Wk = (const float*)d_in[2];
    const float* Wv = (const float*)d_in[3];
    const float* W1 = (const float*)d_in[4];
    const float* W2 = (const float*)d_in[5];
    float* out = (float*)d_out;

    __half *Xhi,*Xlo,*Wqkv,*W1h,*W2h,*AOhi,*AOlo,*H1hi,*H1lo;
    float *QKVlin,*AO;
    cudaGetSymbolAddress((void**)&Xhi, g_Xhi);   cudaGetSymbolAddress((void**)&Xlo, g_Xlo);
    cudaGetSymbolAddress((void**)&Wqkv, g_Wqkv);
    cudaGetSymbolAddress((void**)&W1h, g_W1);    cudaGetSymbolAddress((void**)&W2h, g_W2);
    cudaGetSymbolAddress((void**)&AOhi, g_AOhi); cudaGetSymbolAddress((void**)&AOlo, g_AOlo);
    cudaGetSymbolAddress((void**)&H1hi, g_H1hi); cudaGetSymbolAddress((void**)&H1lo, g_H1lo);
    cudaGetSymbolAddress((void**)&QKVlin, g_QKVlin);
    cudaGetSymbolAddress((void**)&AO, g_AO);

    cudaFuncSetAttribute(mma_gemm<0>, cudaFuncAttributeMaxDynamicSharedMemorySize, GEMM_SMEM);
    cudaFuncSetAttribute(mma_gemm<1>, cudaFuncAttributeMaxDynamicSharedMemorySize, GEMM_SMEM);
    cudaFuncSetAttribute(attn_kernel, cudaFuncAttributeMaxDynamicSharedMemorySize, ATTN_SMEM);

    // 0) RoPE table (double-precision accurate, tiny)
    rope_table_kernel<<<(Tv*32 + 255)/256, 256>>>();

    // 1) operand conversions: A-side hi/lo fp16 split, B-side fp16
    split_kernel<<<(Mtok*Dm/8 + 255)/256, 256>>>((const float4*)X, (uint4*)Xhi, (uint4*)Xlo, Mtok*Dm);
    cvt_kernel<<<(Dm*Dm/8 + 255)/256, 256>>>((const float4*)Wq, (uint4*)Wqkv,              Dm*Dm);
    cvt_kernel<<<(NKV*HD*Dm/8 + 255)/256, 256>>>((const float4*)Wk, (uint4*)(Wqkv + 1024*Dm), NKV*HD*Dm);
    cvt_kernel<<<(NKV*HD*Dm/8 + 255)/256, 256>>>((const float4*)Wv, (uint4*)(Wqkv + 1280*Dm), NKV*HD*Dm);
    cvt_kernel<<<(DFF*Dm/8 + 255)/256, 256>>>((const float4*)W1, (uint4*)W1h, DFF*Dm);
    cvt_kernel<<<(Dm*DFF/8 + 255)/256, 256>>>((const float4*)W2, (uint4*)W2h, Dm*DFF);

    // 2) fused QKV projection: QKVlin = X @ Wqkv^T   (M=4096, N=1536, K=1024)
    mma_gemm<0><<<dim3(NQKV/GBN, Mtok/GBM), 256, GEMM_SMEM>>>(
        Xhi, Xlo, Wqkv, QKVlin, nullptr, nullptr, Mtok, NQKV, Dm);

    // 3) attention: RoPE + permute fused, K/V shared across 4 q-heads
    attn_kernel<<<dim3(Tv/QB, NKV, Bv), 512, ATTN_SMEM>>>(QKVlin, AO);

    // 4) split AO for MLP input
    split_kernel<<<(Mtok*Dm/8 + 255)/256, 256>>>((const float4*)AO, (uint4*)AOhi, (uint4*)AOlo, Mtok*Dm);

    // 5) MLP1: H1 = silu(AO @ W1^T), written as fp16 hi/lo split
    mma_gemm<1><<<dim3(DFF/GBN, Mtok/GBM), 256, GEMM_SMEM>>>(
        AOhi, AOlo, W1h, nullptr, H1hi, H1lo, Mtok, DFF, Dm);

    // 6) MLP2: out = H1 @ W2^T (fp32)
    mma_gemm<0><<<dim3(Dm/GBN, Mtok/GBM), 256, GEMM_SMEM>>>(
        H1hi, H1lo, W2h, out, nullptr, nullptr, Mtok, Dm, DFF);
}

// round 14
// speedup vs baseline: 1.3756x; 1.3756x over previous
#include <cuda_runtime.h>
#include <cuda_fp16.h>
#include <math.h>
#include <stdint.h>

// Problem constants
#define Bv   2
#define Tv   2048
#define Dm   1024
#define NH   16
#define NKV  4
#define HD   64
#define WIN  128
#define Mtok (Bv*Tv)        // 4096
#define DFF  (4*Dm)         // 4096
#define NQKV 1536           // 1024 Q + 256 K + 256 V

// ---------------- scratch (device globals) ---------------------------------
__device__ __align__(256) __half g_Xh[Mtok*Dm];
__device__ __align__(256) __half g_Wqkv[NQKV*Dm];
__device__ __align__(256) __half g_W1[(size_t)DFF*Dm];
__device__ __align__(256) __half g_W2[(size_t)Dm*DFF];
__device__ __align__(256) __half g_AOh[Mtok*Dm];
__device__ __align__(256) __half g_H1h[(size_t)Mtok*DFF];
__device__ __align__(256) float g_QKVlin[(size_t)Mtok*NQKV];
__device__ __align__(256) float g_AO[Mtok*Dm];
__device__ float g_cosT[Tv*32], g_sinT[Tv*32];

// ---------------- helpers ---------------------------------------------------
__device__ __forceinline__ uint32_t smem_u32(const void* p) {
    uint32_t a;
    asm("{ .reg .u64 t; cvta.to.shared.u64 t, %1; cvt.u32.u64 %0, t; }" : "=r"(a) : "l"(p));
    return a;
}
#define LDMX4(r0,r1,r2,r3,addr) \
    asm volatile("ldmatrix.sync.aligned.m8n8.x4.shared.b16 {%0,%1,%2,%3}, [%4];" \
        : "=r"(r0), "=r"(r1), "=r"(r2), "=r"(r3) : "r"(addr))
#define MMA16816(d, a, b) \
    asm volatile("mma.sync.aligned.m16n8k16.row.col.f32.f16.f16.f32 " \
        "{%0,%1,%2,%3}, {%4,%5,%6,%7}, {%8,%9}, {%0,%1,%2,%3};" \
        : "+f"((d)[0]), "+f"((d)[1]), "+f"((d)[2]), "+f"((d)[3]) \
        : "r"((a)[0]), "r"((a)[1]), "r"((a)[2]), "r"((a)[3]), "r"((b)[0]), "r"((b)[1]))

__device__ __forceinline__ uint32_t pack_h2(float x, float y) {
    __half2 h = __floats2half2_rn(x, y);
    return *(uint32_t*)&h;
}

// ---------------- warp-MMA fp16 GEMM (single pass) --------------------------
// C[M,N] = A[M,K] @ B[N,K]^T, A/B fp16, fp32 accumulate.
// EPI 0: write fp32 Cf.  EPI 1: write SiLU(acc) as fp16 Ch.
#define GBM 128
#define GBN 128
#define GBK 32
#define KP  40                      // padded row length (halves) -> 80B stride
#define TILEB (128*KP*2)            // 10240 B per tile
#define STAGE (2*TILEB)             // A, B
#define GEMM_SMEM (3*STAGE)         // 61440 B (3-stage pipeline)

template<int EPI>
__global__ __launch_bounds__(256,2)
void mma_gemm(const __half* __restrict__ Ah, const __half* __restrict__ Bh,
              float* __restrict__ Cf, __half* __restrict__ Ch,
              int M, int N, int K)
{
    extern __shared__ char dsm[];
    const uint32_t sbase = smem_u32(dsm);
    const int tid   = threadIdx.x;
    const int lane  = tid & 31;
    const int wid   = tid >> 5;
    const int warpM = wid & 1;          // 2 x 64 rows
    const int warpN = wid >> 1;         // 4 x 32 cols
    const int bm    = blockIdx.y * GBM;
    const int bn    = blockIdx.x * GBN;

    const __half* gp[2] = {Ah, Bh};

    // 1024 16B chunks per stage (2 tiles x 128 rows x 4 segs)
    auto load_stage = [&](int chunk, int buf) {
        const uint32_t st = sbase + buf * STAGE;
        const int k0 = chunk * GBK;
        #pragma unroll
        for (int i = 0; i < 4; i++) {
            int c   = i * 256 + tid;
            int t2  = c >> 9;
            int r   = (c >> 2) & 127;
            int s   = c & 3;
            int grow = (t2 == 0 ? bm : bn) + r;
            const char* src = (const char*)(gp[t2] + (size_t)grow * K + k0 + s * 8);
            uint32_t dst = st + t2 * TILEB + r * (KP * 2) + s * 16;
            asm volatile("cp.async.cg.shared.global [%0], [%1], 16;" :: "r"(dst), "l"(src));
        }
        asm volatile("cp.async.commit_group;" ::: "memory");
    };

    float acc[4][4][4];
    #pragma unroll
    for (int i = 0; i < 4; i++)
        #pragma unroll
        for (int j = 0; j < 4; j++)
            #pragma unroll
            for (int q = 0; q < 4; q++) acc[i][j][q] = 0.f;

    const int arow = (lane & 7) + 8 * ((lane >> 3) & 1);
    const int acol = 8 * (lane >> 4);
    const int brow = (lane & 7) + 8 * (lane >> 4);
    const int bcol = 8 * ((lane >> 3) & 1);

    const int C = K / GBK;
    load_stage(0, 0);
    load_stage(1, 1);

    for (int c = 0; c < C; c++) {
        const int buf = c % 3;
        if (c + 2 < C) load_stage(c + 2, (c + 2) % 3);

        if (c + 2 < C)      asm volatile("cp.async.wait_group 2;" ::: "memory");
        else if (c + 1 < C) asm volatile("cp.async.wait_group 1;" ::: "memory");
        else                asm volatile("cp.async.wait_group 0;" ::: "memory");
        __syncthreads();

        const uint32_t sA = sbase + buf * STAGE;
        const uint32_t sB = sA + TILEB;

        #pragma unroll
        for (int ks = 0; ks < 2; ks++) {
            const int kb = ks * 16;
            uint32_t a[4][4], bh[4][2];

            #pragma unroll
            for (int nf2 = 0; nf2 < 2; nf2++) {
                uint32_t bd = sB + (((warpN * 32 + nf2 * 16 + brow) * KP) + kb + bcol) * 2;
                LDMX4(bh[nf2*2][0], bh[nf2*2][1], bh[nf2*2+1][0], bh[nf2*2+1][1], bd);
            }
            #pragma unroll
            for (int mf = 0; mf < 4; mf++) {
                uint32_t ad = sA + (((warpM * 64 + mf * 16 + arow) * KP) + kb + acol) * 2;
                LDMX4(a[mf][0], a[mf][1], a[mf][2], a[mf][3], ad);
            }
            #pragma unroll
            for (int mf = 0; mf < 4; mf++)
                #pragma unroll
                for (int nf = 0; nf < 4; nf++)
                    MMA16816(acc[mf][nf], a[mf], bh[nf]);
        }
        __syncthreads();
    }

    const int g = lane >> 2, i4 = lane & 3;
    #pragma unroll
    for (int mf = 0; mf < 4; mf++) {
        #pragma unroll
        for (int nf = 0; nf < 4; nf++) {
            int row0 = bm + warpM * 64 + mf * 16 + g;
            int col  = bn + warpN * 32 + nf * 8 + 2 * i4;
            float d0 = acc[mf][nf][0], d1 = acc[mf][nf][1];
            float d2 = acc[mf][nf][2], d3 = acc[mf][nf][3];
            if (EPI == 0) {
                *(float2*)&Cf[(size_t)row0 * N + col]       = make_float2(d0, d1);
                *(float2*)&Cf[(size_t)(row0 + 8) * N + col] = make_float2(d2, d3);
            } else {
                float a0 = d0 / (1.f + __expf(-d0));
                float a1 = d1 / (1.f + __expf(-d1));
                float a2 = d2 / (1.f + __expf(-d2));
                float a3 = d3 / (1.f + __expf(-d3));
                *(uint32_t*)&Ch[(size_t)row0 * N + col]       = pack_h2(a0, a1);
                *(uint32_t*)&Ch[(size_t)(row0 + 8) * N + col] = pack_h2(a2, a3);
            }
        }
    }
}

// ---------------- fp32 -> fp16 convert (8 floats/thread) -------------------
__global__ void cvt_kernel(const float4* __restrict__ in, uint4* __restrict__ out, int n)
{
    int i = blockIdx.x * 256 + threadIdx.x;
    if (i * 8 >= n) return;
    float4 v0 = in[2*i], v1 = in[2*i+1];
    uint4 O;
    O.x = pack_h2(v0.x, v0.y); O.y = pack_h2(v0.z, v0.w);
    O.z = pack_h2(v1.x, v1.y); O.w = pack_h2(v1.z, v1.w);
    out[i] = O;
}

// ---------------- RoPE table ------------------------------------------------
__global__ void rope_table_kernel()
{
    int idx = blockIdx.x * 256 + threadIdx.x;
    if (idx >= Tv * 32) return;
    int t = idx >> 5, d = idx & 31;
    double invf = pow(10000.0, -(double)d / 32.0);
    double ang  = fmod((double)t * invf, 6.283185307179586476925287);
    g_cosT[idx] = (float)cos(ang);
    g_sinT[idx] = (float)sin(ang);
}

// ---------------- sliding-window GQA attention (fused RoPE, K/V shared) ----
#define QB   8
#define NR   (WIN + QB - 1)    // 135
#define KSTR 68
#define ATTN_SMEM ((NR*KSTR + NR*HD + 4*QB*HD) * (int)sizeof(float))  // 79472

__global__ __launch_bounds__(512) void attn_kernel(const float* __restrict__ QKV,
                                                   float* __restrict__ O)
{
    extern __shared__ float smem[];
    float* Ks = smem;                    // [NR][KSTR]  (roped K)
    float* Vs = Ks + NR * KSTR;          // [NR][64]
    float* Qs = Vs + NR * HD;            // [4][QB][64] (roped Q)

    const int b    = blockIdx.z;
    const int kvh  = blockIdx.y;
    const int qs   = blockIdx.x * QB;
    const int tid  = threadIdx.x;
    const int lane = tid & 31;
    const int wid  = tid >> 5;           // 16 warps
    const int hh   = wid >> 2;           // head within kv group (0..3)
    const int wq   = wid & 3;            // base query index

    const int kbase = qs - (WIN - 1);

    for (int idx = tid; idx < NR * 32; idx += 512) {
        int j = idx >> 5, d = idx & 31;
        int kidx = kbase + j;
        float o1 = 0.f, o2 = 0.f;
        if (kidx >= 0) {
            const float* row = QKV + (size_t)(b * Tv + kidx) * NQKV + 1024 + kvh * HD;
            float x1 = row[d], x2 = row[d + 32];
            float cs = g_cosT[kidx * 32 + d], sn = g_sinT[kidx * 32 + d];
            o1 = x1 * cs - x2 * sn;
            o2 = x1 * sn + x2 * cs;
        }
        Ks[j * KSTR + d]      = o1;
        Ks[j * KSTR + d + 32] = o2;
    }
    for (int idx = tid; idx < NR * HD; idx += 512) {
        int j = idx >> 6, d = idx & 63;
        int kidx = kbase + j;
        float vv = 0.f;
        if (kidx >= 0)
            vv = QKV[(size_t)(b * Tv + kidx) * NQKV + 1280 + kvh * HD + d];
        Vs[j * HD + d] = vv;
    }
    for (int idx = tid; idx < 4 * QB * 32; idx += 512) {
        int hl = idx >> 8, r = (idx >> 5) & 7, d = idx & 31;
        int t = qs + r;
        const float* row = QKV + (size_t)(b * Tv + t) * NQKV + (kvh * 4 + hl) * HD;
        float x1 = row[d], x2 = row[d + 32];
        float cs = g_cosT[t * 32 + d], sn = g_sinT[t * 32 + d];
        Qs[(hl * QB + r) * HD + d]      = x1 * cs - x2 * sn;
        Qs[(hl * QB + r) * HD + d + 32] = x1 * sn + x2 * cs;
    }
    __syncthreads();

    const int h = kvh * 4 + hh;
    #pragma unroll
    for (int qq = 0; qq < 2; qq++) {
        const int wr = wq + qq * 4;
        const int qi = qs + wr;

        float4 qreg[16];
        const float4* q4 = (const float4*)(Qs + (hh * QB + wr) * HD);
        #pragma unroll
        for (int i = 0; i < 16; i++) qreg[i] = q4[i];

        float sc[4];
        #pragma unroll
        for (int c = 0; c < 4; c++) {
            int l = lane + 32 * c;
            int kidx = qi - (WIN - 1) + l;
            if (kidx >= 0) {
                const float4* k4 = (const float4*)(Ks + (wr + l) * KSTR);
                float acc = 0.f;
                #pragma unroll
                for (int i = 0; i < 16; i++) {
                    float4 kk = k4[i];
                    acc += qreg[i].x*kk.x + qreg[i].y*kk.y + qreg[i].z*kk.z + qreg[i].w*kk.w;
                }
                sc[c] = acc * 0.125f;
            } else {
                sc[c] = -INFINITY;
            }
        }

        float m = fmaxf(fmaxf(sc[0], sc[1]), fmaxf(sc[2], sc[3]));
        #pragma unroll
        for (int off = 16; off >= 1; off >>= 1)
            m = fmaxf(m, __shfl_xor_sync(0xffffffffu, m, off));
        float p[4]; float sum = 0.f;
        #pragma unroll
        for (int c = 0; c < 4; c++) { p[c] = __expf(sc[c] - m); sum += p[c]; }
        #pragma unroll
        for (int off = 16; off >= 1; off >>= 1)
            sum += __shfl_xor_sync(0xffffffffu, sum, off);
        const float inv = 1.f / sum;
        #pragma unroll
        for (int c = 0; c < 4; c++) p[c] *= inv;

        float o0 = 0.f, o1 = 0.f;
        #pragma unroll 4
        for (int l = 0; l < WIN; l++) {
            float w = __shfl_sync(0xffffffffu, p[l >> 5], l & 31);
            const float* vrow = Vs + (wr + l) * HD;
            o0 = fmaf(w, vrow[lane],      o0);
            o1 = fmaf(w, vrow[lane + 32], o1);
        }
        float* orow = O + ((size_t)(b * Tv + qi)) * Dm + h * HD;
        orow[lane]      = o0;
        orow[lane + 32] = o1;
    }
}

// ---------------- launch ----------------------------------------------------
extern "C" void kernel_launch(void* const* d_in, const int* in_sizes, int n_in,
                              void* d_out, int out_size)
{
    const float* X  = (const float*)d_in[0];
    const float* Wq = (const float*)d_in[1];
    const float* Wk = (const float*)d_in[2];
    const float* Wv = (const float*)d_in[3];
    const float* W1 = (const float*)d_in[4];
    const float* W2 = (const float*)d_in[5];
    float* out = (float*)d_out;

    __half *Xh,*Wqkv,*W1h,*W2h,*AOh,*H1h;
    float *QKVlin,*AO;
    cudaGetSymbolAddress((void**)&Xh, g_Xh);
    cudaGetSymbolAddress((void**)&Wqkv, g_Wqkv);
    cudaGetSymbolAddress((void**)&W1h, g_W1);    cudaGetSymbolAddress((void**)&W2h, g_W2);
    cudaGetSymbolAddress((void**)&AOh, g_AOh);   cudaGetSymbolAddress((void**)&H1h, g_H1h);
    cudaGetSymbolAddress((void**)&QKVlin, g_QKVlin);
    cudaGetSymbolAddress((void**)&AO, g_AO);

    cudaFuncSetAttribute(mma_gemm<0>, cudaFuncAttributeMaxDynamicSharedMemorySize, GEMM_SMEM);
    cudaFuncSetAttribute(mma_gemm<1>, cudaFuncAttributeMaxDynamicSharedMemorySize, GEMM_SMEM);
    cudaFuncSetAttribute(attn_kernel, cudaFuncAttributeMaxDynamicSharedMemorySize, ATTN_SMEM);

    // 0) RoPE table (double-precision accurate, tiny)
    rope_table_kernel<<<(Tv*32 + 255)/256, 256>>>();

    // 1) fp16 conversions
    cvt_kernel<<<(Mtok*Dm/8 + 255)/256, 256>>>((const float4*)X, (uint4*)Xh, Mtok*Dm);
    cvt_kernel<<<(Dm*Dm/8 + 255)/256, 256>>>((const float4*)Wq, (uint4*)Wqkv,              Dm*Dm);
    cvt_kernel<<<(NKV*HD*Dm/8 + 255)/256, 256>>>((const float4*)Wk, (uint4*)(Wqkv + 1024*Dm), NKV*HD*Dm);
    cvt_kernel<<<(NKV*HD*Dm/8 + 255)/256, 256>>>((const float4*)Wv, (uint4*)(Wqkv + 1280*Dm), NKV*HD*Dm);
    cvt_kernel<<<(DFF*Dm/8 + 255)/256, 256>>>((const float4*)W1, (uint4*)W1h, DFF*Dm);
    cvt_kernel<<<(Dm*DFF/8 + 255)/256, 256>>>((const float4*)W2, (uint4*)W2h, Dm*DFF);

    // 2) fused QKV projection: QKVlin = X @ Wqkv^T   (M=4096, N=1536, K=1024)
    mma_gemm<0><<<dim3(NQKV/GBN, Mtok/GBM), 256, GEMM_SMEM>>>(
        Xh, Wqkv, QKVlin, nullptr, Mtok, NQKV, Dm);

    // 3) attention: RoPE + permute fused, K/V shared across 4 q-heads
    attn_kernel<<<dim3(Tv/QB, NKV, Bv), 512, ATTN_SMEM>>>(QKVlin, AO);

    // 4) convert AO to fp16
    cvt_kernel<<<(Mtok*Dm/8 + 255)/256, 256>>>((const float4*)AO, (uint4*)AOh, Mtok*Dm);

    // 5) MLP1: H1 = silu(AO @ W1^T) -> fp16
    mma_gemm<1><<<dim3(DFF/GBN, Mtok/GBM), 256, GEMM_SMEM>>>(
        AOh, W1h, nullptr, H1h, Mtok, DFF, Dm);

    // 6) MLP2: out = H1 @ W2^T (fp32)
    mma_gemm<0><<<dim3(Dm/GBN, Mtok/GBM), 256, GEMM_SMEM>>>(
        H1h, W2h, out, nullptr, Mtok, Dm, DFF);
}

// round 15
// speedup vs baseline: 1.9377x; 1.4086x over previous
#include <cuda_runtime.h>
#include <cuda_fp16.h>
#include <math.h>
#include <stdint.h>

// Problem constants
#define Bv   2
#define Tv   2048
#define Dm   1024
#define NH   16
#define NKV  4
#define HD   64
#define WIN  128
#define Mtok (Bv*Tv)        // 4096
#define DFF  (4*Dm)         // 4096
#define NQKV 1536           // 1024 Q + 256 K + 256 V

// ---------------- scratch (device globals) ---------------------------------
__device__ __align__(256) __half g_Xh[Mtok*Dm];
__device__ __align__(256) __half g_Wqkv[NQKV*Dm];
__device__ __align__(256) __half g_W1[(size_t)DFF*Dm];
__device__ __align__(256) __half g_W2[(size_t)Dm*DFF];
__device__ __align__(256) __half g_AOh[Mtok*Dm];
__device__ __align__(256) __half g_H1h[(size_t)Mtok*DFF];
__device__ __align__(256) float g_QKVlin[(size_t)Mtok*NQKV];
__device__ float g_cosT[Tv*32], g_sinT[Tv*32];

// ---------------- helpers ---------------------------------------------------
__device__ __forceinline__ uint32_t smem_u32(const void* p) {
    uint32_t a;
    asm("{ .reg .u64 t; cvta.to.shared.u64 t, %1; cvt.u32.u64 %0, t; }" : "=r"(a) : "l"(p));
    return a;
}
#define LDMX4(r0,r1,r2,r3,addr) \
    asm volatile("ldmatrix.sync.aligned.m8n8.x4.shared.b16 {%0,%1,%2,%3}, [%4];" \
        : "=r"(r0), "=r"(r1), "=r"(r2), "=r"(r3) : "r"(addr))
#define LDMX2T(r0,r1,addr) \
    asm volatile("ldmatrix.sync.aligned.m8n8.x2.trans.shared.b16 {%0,%1}, [%2];" \
        : "=r"(r0), "=r"(r1) : "r"(addr))
#define MMA16816(d, a, b) \
    asm volatile("mma.sync.aligned.m16n8k16.row.col.f32.f16.f16.f32 " \
        "{%0,%1,%2,%3}, {%4,%5,%6,%7}, {%8,%9}, {%0,%1,%2,%3};" \
        : "+f"((d)[0]), "+f"((d)[1]), "+f"((d)[2]), "+f"((d)[3]) \
        : "r"((a)[0]), "r"((a)[1]), "r"((a)[2]), "r"((a)[3]), "r"((b)[0]), "r"((b)[1]))

__device__ __forceinline__ uint32_t pack_h2(float x, float y) {
    __half2 h = __floats2half2_rn(x, y);
    return *(uint32_t*)&h;
}

// ---------------- warp-MMA fp16 GEMM (single pass) --------------------------
#define GBM 128
#define GBN 128
#define GBK 32
#define KP  40
#define TILEB (128*KP*2)
#define STAGE (2*TILEB)
#define GEMM_SMEM (3*STAGE)

template<int EPI>
__global__ __launch_bounds__(256,2)
void mma_gemm(const __half* __restrict__ Ah, const __half* __restrict__ Bh,
              float* __restrict__ Cf, __half* __restrict__ Ch,
              int M, int N, int K)
{
    extern __shared__ char dsm[];
    const uint32_t sbase = smem_u32(dsm);
    const int tid   = threadIdx.x;
    const int lane  = tid & 31;
    const int wid   = tid >> 5;
    const int warpM = wid & 1;
    const int warpN = wid >> 1;
    const int bm    = blockIdx.y * GBM;
    const int bn    = blockIdx.x * GBN;

    const __half* gp[2] = {Ah, Bh};

    auto load_stage = [&](int chunk, int buf) {
        const uint32_t st = sbase + buf * STAGE;
        const int k0 = chunk * GBK;
        #pragma unroll
        for (int i = 0; i < 4; i++) {
            int c   = i * 256 + tid;
            int t2  = c >> 9;
            int r   = (c >> 2) & 127;
            int s   = c & 3;
            int grow = (t2 == 0 ? bm : bn) + r;
            const char* src = (const char*)(gp[t2] + (size_t)grow * K + k0 + s * 8);
            uint32_t dst = st + t2 * TILEB + r * (KP * 2) + s * 16;
            asm volatile("cp.async.cg.shared.global [%0], [%1], 16;" :: "r"(dst), "l"(src));
        }
        asm volatile("cp.async.commit_group;" ::: "memory");
    };

    float acc[4][4][4];
    #pragma unroll
    for (int i = 0; i < 4; i++)
        #pragma unroll
        for (int j = 0; j < 4; j++)
            #pragma unroll
            for (int q = 0; q < 4; q++) acc[i][j][q] = 0.f;

    const int arow = (lane & 7) + 8 * ((lane >> 3) & 1);
    const int acol = 8 * (lane >> 4);
    const int brow = (lane & 7) + 8 * (lane >> 4);
    const int bcol = 8 * ((lane >> 3) & 1);

    const int C = K / GBK;
    load_stage(0, 0);
    load_stage(1, 1);

    for (int c = 0; c < C; c++) {
        const int buf = c % 3;
        if (c + 2 < C) load_stage(c + 2, (c + 2) % 3);

        if (c + 2 < C)      asm volatile("cp.async.wait_group 2;" ::: "memory");
        else if (c + 1 < C) asm volatile("cp.async.wait_group 1;" ::: "memory");
        else                asm volatile("cp.async.wait_group 0;" ::: "memory");
        __syncthreads();

        const uint32_t sA = sbase + buf * STAGE;
        const uint32_t sB = sA + TILEB;

        #pragma unroll
        for (int ks = 0; ks < 2; ks++) {
            const int kb = ks * 16;
            uint32_t a[4][4], bh[4][2];

            #pragma unroll
            for (int nf2 = 0; nf2 < 2; nf2++) {
                uint32_t bd = sB + (((warpN * 32 + nf2 * 16 + brow) * KP) + kb + bcol) * 2;
                LDMX4(bh[nf2*2][0], bh[nf2*2][1], bh[nf2*2+1][0], bh[nf2*2+1][1], bd);
            }
            #pragma unroll
            for (int mf = 0; mf < 4; mf++) {
                uint32_t ad = sA + (((warpM * 64 + mf * 16 + arow) * KP) + kb + acol) * 2;
                LDMX4(a[mf][0], a[mf][1], a[mf][2], a[mf][3], ad);
            }
            #pragma unroll
            for (int mf = 0; mf < 4; mf++)
                #pragma unroll
                for (int nf = 0; nf < 4; nf++)
                    MMA16816(acc[mf][nf], a[mf], bh[nf]);
        }
        __syncthreads();
    }

    const int g = lane >> 2, i4 = lane & 3;
    #pragma unroll
    for (int mf = 0; mf < 4; mf++) {
        #pragma unroll
        for (int nf = 0; nf < 4; nf++) {
            int row0 = bm + warpM * 64 + mf * 16 + g;
            int col  = bn + warpN * 32 + nf * 8 + 2 * i4;
            float d0 = acc[mf][nf][0], d1 = acc[mf][nf][1];
            float d2 = acc[mf][nf][2], d3 = acc[mf][nf][3];
            if (EPI == 0) {
                *(float2*)&Cf[(size_t)row0 * N + col]       = make_float2(d0, d1);
                *(float2*)&Cf[(size_t)(row0 + 8) * N + col] = make_float2(d2, d3);
            } else {
                float a0 = d0 / (1.f + __expf(-d0));
                float a1 = d1 / (1.f + __expf(-d1));
                float a2 = d2 / (1.f + __expf(-d2));
                float a3 = d3 / (1.f + __expf(-d3));
                *(uint32_t*)&Ch[(size_t)row0 * N + col]       = pack_h2(a0, a1);
                *(uint32_t*)&Ch[(size_t)(row0 + 8) * N + col] = pack_h2(a2, a3);
            }
        }
    }
}

// ---------------- fp32 -> fp16 convert (8 floats/thread) -------------------
__global__ void cvt_kernel(const float4* __restrict__ in, uint4* __restrict__ out, int n)
{
    int i = blockIdx.x * 256 + threadIdx.x;
    if (i * 8 >= n) return;
    float4 v0 = in[2*i], v1 = in[2*i+1];
    uint4 O;
    O.x = pack_h2(v0.x, v0.y); O.y = pack_h2(v0.z, v0.w);
    O.z = pack_h2(v1.x, v1.y); O.w = pack_h2(v1.z, v1.w);
    out[i] = O;
}

// ---------------- RoPE table ------------------------------------------------
__global__ void rope_table_kernel()
{
    int idx = blockIdx.x * 256 + threadIdx.x;
    if (idx >= Tv * 32) return;
    int t = idx >> 5, d = idx & 31;
    double invf = pow(10000.0, -(double)d / 32.0);
    double ang  = fmod((double)t * invf, 6.283185307179586476925287);
    g_cosT[idx] = (float)cos(ang);
    g_sinT[idx] = (float)sin(ang);
}

// ---------------- MMA flash attention --------------------------------------
// Block: 1 kv-head x 16 queries; 4 compute warps (one q-head each), 8 warps load.
// S[16x144] = (Qhi+Qlo)@(Khi+Klo)^T (3 passes, fp32 acc); softmax in fragments;
// O = P@(Vhi+Vlo) (2 passes); write fp16 AOh directly.
#define AQ    16
#define ANK   144              // key range: qs-127 .. qs+16
#define APAD  72               // halves per row (144B stride, conflict-free ldmatrix)
#define ATTN_SMEM ((4*ANK*APAD + 2*64*APAD) * 2)   // 101376 B

__global__ __launch_bounds__(256,1) void attn_kernel(const float* __restrict__ QKV,
                                                     __half* __restrict__ AOh)
{
    extern __shared__ __half hsm[];
    __half* Khi = hsm;
    __half* Klo = Khi + ANK*APAD;
    __half* Vhi = Klo + ANK*APAD;
    __half* Vlo = Vhi + ANK*APAD;
    __half* Qhi = Vlo + ANK*APAD;     // [64][APAD] rows = head*16 + r
    __half* Qlo = Qhi + 64*APAD;

    const int b    = blockIdx.z;
    const int kvh  = blockIdx.y;
    const int qs   = blockIdx.x * AQ;
    const int tid  = threadIdx.x;
    const int lane = tid & 31;
    const int wid  = tid >> 5;
    const int kbase = qs - (WIN - 1);

    // ---- loads (all 8 warps) ----
    for (int idx = tid; idx < ANK * 32; idx += 256) {   // K with rope
        int j = idx >> 5, d = idx & 31;
        int kidx = kbase + j;
        float o1 = 0.f, o2 = 0.f;
        if (kidx >= 0 && kidx < Tv) {
            const float* row = QKV + (size_t)(b * Tv + kidx) * NQKV + 1024 + kvh * HD;
            float x1 = row[d], x2 = row[d + 32];
            float cs = g_cosT[kidx * 32 + d], sn = g_sinT[kidx * 32 + d];
            o1 = x1 * cs - x2 * sn;
            o2 = x1 * sn + x2 * cs;
        }
        __half h1 = __float2half_rn(o1), h2 = __float2half_rn(o2);
        Khi[j * APAD + d]      = h1;
        Khi[j * APAD + d + 32] = h2;
        Klo[j * APAD + d]      = __float2half_rn(o1 - __half2float(h1));
        Klo[j * APAD + d + 32] = __float2half_rn(o2 - __half2float(h2));
    }
    for (int idx = tid; idx < ANK * HD; idx += 256) {   // V split
        int j = idx >> 6, d = idx & 63;
        int kidx = kbase + j;
        float vv = 0.f;
        if (kidx >= 0 && kidx < Tv)
            vv = QKV[(size_t)(b * Tv + kidx) * NQKV + 1280 + kvh * HD + d];
        __half h = __float2half_rn(vv);
        Vhi[j * APAD + d] = h;
        Vlo[j * APAD + d] = __float2half_rn(vv - __half2float(h));
    }
    for (int idx = tid; idx < 64 * 32; idx += 256) {    // Q with rope (4 heads x 16)
        int row = idx >> 5, d = idx & 31;
        int head = row >> 4, r = row & 15;
        int t = qs + r;
        const float* src = QKV + (size_t)(b * Tv + t) * NQKV + (kvh * 4 + head) * HD;
        float x1 = src[d], x2 = src[d + 32];
        float cs = g_cosT[t * 32 + d], sn = g_sinT[t * 32 + d];
        float o1 = x1 * cs - x2 * sn;
        float o2 = x1 * sn + x2 * cs;
        __half h1 = __float2half_rn(o1), h2 = __float2half_rn(o2);
        Qhi[row * APAD + d]      = h1;
        Qhi[row * APAD + d + 32] = h2;
        Qlo[row * APAD + d]      = __float2half_rn(o1 - __half2float(h1));
        Qlo[row * APAD + d + 32] = __float2half_rn(o2 - __half2float(h2));
    }
    __syncthreads();
    if (wid >= 4) return;                    // 4 compute warps remain; no more syncs

    const uint32_t sKhi = smem_u32(Khi), sKlo = smem_u32(Klo);
    const uint32_t sVhi = smem_u32(Vhi), sVlo = smem_u32(Vlo);
    const uint32_t sQhi = smem_u32(Qhi), sQlo = smem_u32(Qlo);

    const int g = lane >> 2, i4 = lane & 3;
    const int arow = (lane & 7) + 8 * ((lane >> 3) & 1);
    const int acol = 8 * (lane >> 4);
    const int brow = (lane & 7) + 8 * (lane >> 4);
    const int bcol = 8 * ((lane >> 3) & 1);

    float S[18][4];
    #pragma unroll
    for (int t = 0; t < 18; t++)
        #pragma unroll
        for (int e = 0; e < 4; e++) S[t][e] = 0.f;

    // ---- scores: 3 passes (QhiKhi, QhiKlo, QloKhi) ----
    #pragma unroll
    for (int pass = 0; pass < 3; pass++) {
        const uint32_t sQ = (pass == 2) ? sQlo : sQhi;
        const uint32_t sK = (pass == 1) ? sKlo : sKhi;
        #pragma unroll
        for (int ks = 0; ks < 4; ks++) {
            const int kb = ks * 16;
            uint32_t a[4];
            uint32_t ad = sQ + ((wid * 16 + arow) * APAD + kb + acol) * 2;
            LDMX4(a[0], a[1], a[2], a[3], ad);
            #pragma unroll
            for (int bt = 0; bt < 9; bt++) {
                uint32_t bh[2][2];
                uint32_t bd = sK + ((bt * 16 + brow) * APAD + kb + bcol) * 2;
                LDMX4(bh[0][0], bh[0][1], bh[1][0], bh[1][1], bd);
                MMA16816(S[bt*2],     a, bh[0]);
                MMA16816(S[bt*2 + 1], a, bh[1]);
            }
        }
    }

    // ---- mask + scale ----
    #pragma unroll
    for (int t = 0; t < 18; t++) {
        #pragma unroll
        for (int e = 0; e < 2; e++) {
            int n = t * 8 + 2 * i4 + e;
            int kidx = kbase + n;
            // row g
            if (n < g || n > g + 127 || kidx < 0) S[t][e] = -1e30f;
            else S[t][e] *= 0.125f;
            // row g+8
            int r1 = g + 8;
            if (n < r1 || n > r1 + 127 || kidx < 0) S[t][2+e] = -1e30f;
            else S[t][2+e] *= 0.125f;
        }
    }

    // ---- softmax (rows g and g+8), quad reduction over i4 ----
    float m0 = -1e30f, m1 = -1e30f;
    #pragma unroll
    for (int t = 0; t < 18; t++) {
        m0 = fmaxf(m0, fmaxf(S[t][0], S[t][1]));
        m1 = fmaxf(m1, fmaxf(S[t][2], S[t][3]));
    }
    #pragma unroll
    for (int off = 1; off <= 2; off <<= 1) {
        m0 = fmaxf(m0, __shfl_xor_sync(0xffffffffu, m0, off));
        m1 = fmaxf(m1, __shfl_xor_sync(0xffffffffu, m1, off));
    }
    float s0 = 0.f, s1 = 0.f;
    uint32_t Pg[18], Pg8[18];
    #pragma unroll
    for (int t = 0; t < 18; t++) {
        float p0 = __expf(S[t][0] - m0), p1 = __expf(S[t][1] - m0);
        float p2 = __expf(S[t][2] - m1), p3 = __expf(S[t][3] - m1);
        s0 += p0 + p1;  s1 += p2 + p3;
        Pg[t]  = pack_h2(p0, p1);
        Pg8[t] = pack_h2(p2, p3);
    }
    #pragma unroll
    for (int off = 1; off <= 2; off <<= 1) {
        s0 += __shfl_xor_sync(0xffffffffu, s0, off);
        s1 += __shfl_xor_sync(0xffffffffu, s1, off);
    }

    // ---- PV: O[16x64] = P @ (Vhi + Vlo) ----
    float O[8][4];
    #pragma unroll
    for (int dt = 0; dt < 8; dt++)
        #pragma unroll
        for (int e = 0; e < 4; e++) O[dt][e] = 0.f;

    #pragma unroll
    for (int kt = 0; kt < 9; kt++) {
        uint32_t a[4] = { Pg[2*kt], Pg8[2*kt], Pg[2*kt+1], Pg8[2*kt+1] };
        const uint32_t rowoff = (uint32_t)((kt * 16 + (lane & 15)) * APAD) * 2;
        #pragma unroll
        for (int dt = 0; dt < 8; dt++) {
            uint32_t bv[2];
            LDMX2T(bv[0], bv[1], sVhi + rowoff + dt * 16);
            MMA16816(O[dt], a, bv);
            LDMX2T(bv[0], bv[1], sVlo + rowoff + dt * 16);
            MMA16816(O[dt], a, bv);
        }
    }

    // ---- epilogue: normalize + write fp16 AOh ----
    const float inv0 = 1.f / s0, inv1 = 1.f / s1;
    const int h = kvh * 4 + wid;
    const size_t base0 = (size_t)(b * Tv + qs + g)     * Dm + h * HD;
    const size_t base1 = (size_t)(b * Tv + qs + g + 8) * Dm + h * HD;
    #pragma unroll
    for (int dt = 0; dt < 8; dt++) {
        int col = dt * 8 + 2 * i4;
        *(uint32_t*)&AOh[base0 + col] = pack_h2(O[dt][0] * inv0, O[dt][1] * inv0);
        *(uint32_t*)&AOh[base1 + col] = pack_h2(O[dt][2] * inv1, O[dt][3] * inv1);
    }
}

// ---------------- launch ----------------------------------------------------
extern "C" void kernel_launch(void* const* d_in, const int* in_sizes, int n_in,
                              void* d_out, int out_size)
{
    const float* X  = (const float*)d_in[0];
    const float* Wq = (const float*)d_in[1];
    const float* Wk = (const float*)d_in[2];
    const float* Wv = (const float*)d_in[3];
    const float* W1 = (const float*)d_in[4];
    const float* W2 = (const float*)d_in[5];
    float* out = (float*)d_out;

    __half *Xh,*Wqkv,*W1h,*W2h,*AOh,*H1h;
    float *QKVlin;
    cudaGetSymbolAddress((void**)&Xh, g_Xh);
    cudaGetSymbolAddress((void**)&Wqkv, g_Wqkv);
    cudaGetSymbolAddress((void**)&W1h, g_W1);    cudaGetSymbolAddress((void**)&W2h, g_W2);
    cudaGetSymbolAddress((void**)&AOh, g_AOh);   cudaGetSymbolAddress((void**)&H1h, g_H1h);
    cudaGetSymbolAddress((void**)&QKVlin, g_QKVlin);

    cudaFuncSetAttribute(mma_gemm<0>, cudaFuncAttributeMaxDynamicSharedMemorySize, GEMM_SMEM);
    cudaFuncSetAttribute(mma_gemm<1>, cudaFuncAttributeMaxDynamicSharedMemorySize, GEMM_SMEM);
    cudaFuncSetAttribute(attn_kernel, cudaFuncAttributeMaxDynamicSharedMemorySize, ATTN_SMEM);

    // 0) RoPE table
    rope_table_kernel<<<(Tv*32 + 255)/256, 256>>>();

    // 1) fp16 conversions
    cvt_kernel<<<(Mtok*Dm/8 + 255)/256, 256>>>((const float4*)X, (uint4*)Xh, Mtok*Dm);
    cvt_kernel<<<(Dm*Dm/8 + 255)/256, 256>>>((const float4*)Wq, (uint4*)Wqkv,              Dm*Dm);
    cvt_kernel<<<(NKV*HD*Dm/8 + 255)/256, 256>>>((const float4*)Wk, (uint4*)(Wqkv + 1024*Dm), NKV*HD*Dm);
    cvt_kernel<<<(NKV*HD*Dm/8 + 255)/256, 256>>>((const float4*)Wv, (uint4*)(Wqkv + 1280*Dm), NKV*HD*Dm);
    cvt_kernel<<<(DFF*Dm/8 + 255)/256, 256>>>((const float4*)W1, (uint4*)W1h, DFF*Dm);
    cvt_kernel<<<(Dm*DFF/8 + 255)/256, 256>>>((const float4*)W2, (uint4*)W2h, Dm*DFF);

    // 2) fused QKV projection: QKVlin = X @ Wqkv^T
    mma_gemm<0><<<dim3(NQKV/GBN, Mtok/GBM), 256, GEMM_SMEM>>>(
        Xh, Wqkv, QKVlin, nullptr, Mtok, NQKV, Dm);

    // 3) MMA flash attention (RoPE fused; writes fp16 AOh)
    attn_kernel<<<dim3(Tv/AQ, NKV, Bv), 256, ATTN_SMEM>>>(QKVlin, AOh);

    // 4) MLP1: H1 = silu(AO @ W1^T) -> fp16
    mma_gemm<1><<<dim3(DFF/GBN, Mtok/GBM), 256, GEMM_SMEM>>>(
        AOh, W1h, nullptr, H1h, Mtok, DFF, Dm);

    // 5) MLP2: out = H1 @ W2^T (fp32)
    mma_gemm<0><<<dim3(Dm/GBN, Mtok/GBM), 256, GEMM_SMEM>>>(
        H1h, W2h, out, nullptr, Mtok, Dm, DFF);
}